// round 1
// baseline (speedup 1.0000x reference)
#include <cuda_runtime.h>

// ---------------- problem constants ----------------
#define NN 100000
#define NE 3200000
#define GG 64

// ---------------- device scratch (no allocs allowed) ----------------
__device__ float g_y[NN * 64];          // dis-scaled x@W
__device__ float g_local[NN * 256];     // concat of 4 layer outputs
__device__ float g_h1[NN * 256];        // enc layer-1 output
__device__ float g_h2[NN * 128];        // enc layer-2 output
__device__ float g_dis[NN];
__device__ int   g_cnt[NN];
__device__ int   g_excl[NN];
__device__ int   g_rowptr[NN + 1];
__device__ int   g_woff[NN];
__device__ int   g_src[NE];
__device__ int   g_bsums[128];
__device__ float g_gsum[GG * 128];
__device__ float g_gcnt[GG];

// ---------------- degree / dis ----------------
__global__ void k_init_cnt(int n) {
    int i = blockIdx.x * blockDim.x + threadIdx.x;
    if (i < n) g_cnt[i] = 1;  // self loop
}

__global__ void k_deg(const int* __restrict__ ei, int ne) {
    int i = blockIdx.x * blockDim.x + threadIdx.x;
    if (i < ne) atomicAdd(&g_cnt[ei[ne + i]], 1);  // col = target
}

__global__ void k_dis(int n) {
    int i = blockIdx.x * blockDim.x + threadIdx.x;
    if (i < n) g_dis[i] = rsqrtf((float)g_cnt[i]);
}

// ---------------- prefix scan for CSR (counts = cnt-1 = in-degree) --------
__global__ void k_scanA(int n) {
    __shared__ int sh[1024];
    int tid = threadIdx.x;
    int i = blockIdx.x * 1024 + tid;
    int v = (i < n) ? (g_cnt[i] - 1) : 0;
    sh[tid] = v;
    __syncthreads();
    for (int off = 1; off < 1024; off <<= 1) {
        int t = (tid >= off) ? sh[tid - off] : 0;
        __syncthreads();
        sh[tid] += t;
        __syncthreads();
    }
    if (i < n) g_excl[i] = sh[tid] - v;  // exclusive within block
    if (tid == 1023) g_bsums[blockIdx.x] = sh[1023];
}

__global__ void k_scanB(int nb) {
    if (threadIdx.x == 0 && blockIdx.x == 0) {
        int run = 0;
        for (int b = 0; b < nb; b++) {
            int t = g_bsums[b];
            g_bsums[b] = run;
            run += t;
        }
    }
}

__global__ void k_scanC(int n, int ne) {
    int i = blockIdx.x * blockDim.x + threadIdx.x;
    if (i < n) {
        int rp = g_excl[i] + g_bsums[i >> 10];
        g_rowptr[i] = rp;
        g_woff[i] = rp;
    }
    if (i == 0) g_rowptr[n] = ne;
}

__global__ void k_scatter(const int* __restrict__ ei, int ne) {
    int i = blockIdx.x * blockDim.x + threadIdx.x;
    if (i < ne) {
        int c = ei[ne + i];
        int pos = atomicAdd(&g_woff[c], 1);
        g_src[pos] = ei[i];  // row = source
    }
}

// ---------------- conv GEMM: y = (Xin @ W_l) * dis[row] ----------------
// block: 64 rows x 64 cols, 256 threads, 4x4 per thread
__global__ __launch_bounds__(256) void k_conv_gemm(
    const float* __restrict__ X0, const float* __restrict__ W,
    int n, int layer) {
    __shared__ float As[64][65];
    __shared__ float Ws[64][64];
    int tid = threadIdx.x;
    int rowBase = blockIdx.x * 64;

    for (int idx = tid; idx < 4096; idx += 256)
        Ws[idx >> 6][idx & 63] = W[idx];
    for (int idx = tid; idx < 4096; idx += 256) {
        int r = idx >> 6, k = idx & 63;
        int gr = rowBase + r;
        float v = 0.f;
        if (gr < n) {
            if (layer == 0) v = X0[gr * 64 + k];
            else            v = g_local[gr * 256 + (layer - 1) * 64 + k];
        }
        As[r][k] = v;
    }
    __syncthreads();

    int tx = tid & 15, ty = tid >> 4;
    int c4 = tx * 4, r0 = ty * 4;
    float acc[4][4] = {};
#pragma unroll
    for (int k = 0; k < 64; k++) {
        float4 b = *(const float4*)&Ws[k][c4];
        float a0 = As[r0 + 0][k];
        float a1 = As[r0 + 1][k];
        float a2 = As[r0 + 2][k];
        float a3 = As[r0 + 3][k];
        acc[0][0] += a0 * b.x; acc[0][1] += a0 * b.y; acc[0][2] += a0 * b.z; acc[0][3] += a0 * b.w;
        acc[1][0] += a1 * b.x; acc[1][1] += a1 * b.y; acc[1][2] += a1 * b.z; acc[1][3] += a1 * b.w;
        acc[2][0] += a2 * b.x; acc[2][1] += a2 * b.y; acc[2][2] += a2 * b.z; acc[2][3] += a2 * b.w;
        acc[3][0] += a3 * b.x; acc[3][1] += a3 * b.y; acc[3][2] += a3 * b.z; acc[3][3] += a3 * b.w;
    }
#pragma unroll
    for (int i = 0; i < 4; i++) {
        int gr = rowBase + r0 + i;
        if (gr < n) {
            float d = g_dis[gr];
            float4 v;
            v.x = acc[i][0] * d; v.y = acc[i][1] * d;
            v.z = acc[i][2] * d; v.w = acc[i][3] * d;
            *(float4*)&g_y[gr * 64 + c4] = v;
        }
    }
}

// ---------------- aggregation + BN + relu + skip (warp per node) ----------
__global__ __launch_bounds__(256) void k_agg(
    int n, int layer,
    const float* __restrict__ bias, const float* __restrict__ gamma,
    const float* __restrict__ beta, const float* __restrict__ mean,
    const float* __restrict__ var) {
    int warp = (blockIdx.x * blockDim.x + threadIdx.x) >> 5;
    int lane = threadIdx.x & 31;
    if (warp >= n) return;
    int c = warp;
    int start = g_rowptr[c], end = g_rowptr[c + 1];
    float acc0 = g_y[c * 64 + lane];          // self loop
    float acc1 = g_y[c * 64 + 32 + lane];
    for (int e = start; e < end; e++) {
        int r = g_src[e];
        acc0 += g_y[r * 64 + lane];
        acc1 += g_y[r * 64 + 32 + lane];
    }
    float dc = g_dis[c];
    int d0 = lane, d1 = lane + 32;

    float s0 = gamma[d0] * rsqrtf(var[d0] + 1e-5f);
    float s1 = gamma[d1] * rsqrtf(var[d1] + 1e-5f);
    float v0 = (acc0 * dc + bias[d0] - mean[d0]) * s0 + beta[d0];
    float v1 = (acc1 * dc + bias[d1] - mean[d1]) * s1 + beta[d1];
    v0 = fmaxf(v0, 0.f);
    v1 = fmaxf(v1, 0.f);
    if (layer == 2) {  // skip: += previous_outputs[0] (cols 0..63)
        v0 += g_local[c * 256 + d0];
        v1 += g_local[c * 256 + d1];
    }
    g_local[c * 256 + layer * 64 + d0] = v0;
    g_local[c * 256 + layer * 64 + d1] = v1;
}

// ---------------- encoder GEMMs: out = relu(A @ B + bias) ----------------
// BM=128, BN=128, BK=16; 256 threads; 8x8 per thread.
// mode 0: A=g_local (ld 256), out=g_h1 (ld 256)
// mode 1: A=g_h1    (ld 256), out=g_h2 (ld 128)
__global__ __launch_bounds__(256) void k_enc_gemm(
    const float* __restrict__ B, const float* __restrict__ bias,
    int K, int ncols, int mode, int n) {
    __shared__ float As[128][17];
    __shared__ float Bs[16][128];
    const float* A = (mode == 0) ? g_local : g_h1;
    float* O = (mode == 0) ? g_h1 : g_h2;
    const int lda = 256;
    const int ldo = (mode == 0) ? 256 : 128;
    int rowBase = blockIdx.x * 128;
    int colBase = blockIdx.y * 128;
    int tid = threadIdx.x;
    int tx = tid & 15, ty = tid >> 4;
    float acc[8][8] = {};

    for (int kb = 0; kb < K; kb += 16) {
        for (int idx = tid; idx < 128 * 16; idx += 256) {
            int r = idx >> 4, k = idx & 15;
            int gr = rowBase + r;
            As[r][k] = (gr < n) ? A[gr * lda + kb + k] : 0.f;
        }
        for (int idx = tid; idx < 16 * 128; idx += 256) {
            int r = idx >> 7, cc = idx & 127;
            Bs[r][cc] = B[(kb + r) * ncols + colBase + cc];
        }
        __syncthreads();
#pragma unroll
        for (int k = 0; k < 16; k++) {
            float4 b0 = *(const float4*)&Bs[k][tx * 8];
            float4 b1 = *(const float4*)&Bs[k][tx * 8 + 4];
            float a[8];
#pragma unroll
            for (int i = 0; i < 8; i++) a[i] = As[ty * 8 + i][k];
#pragma unroll
            for (int i = 0; i < 8; i++) {
                acc[i][0] += a[i] * b0.x; acc[i][1] += a[i] * b0.y;
                acc[i][2] += a[i] * b0.z; acc[i][3] += a[i] * b0.w;
                acc[i][4] += a[i] * b1.x; acc[i][5] += a[i] * b1.y;
                acc[i][6] += a[i] * b1.z; acc[i][7] += a[i] * b1.w;
            }
        }
        __syncthreads();
    }
    int cb = colBase + tx * 8;
    float4 bb0 = *(const float4*)&bias[cb];
    float4 bb1 = *(const float4*)&bias[cb + 4];
#pragma unroll
    for (int i = 0; i < 8; i++) {
        int gr = rowBase + ty * 8 + i;
        if (gr < n) {
            float4 v0, v1;
            v0.x = fmaxf(acc[i][0] + bb0.x, 0.f);
            v0.y = fmaxf(acc[i][1] + bb0.y, 0.f);
            v0.z = fmaxf(acc[i][2] + bb0.z, 0.f);
            v0.w = fmaxf(acc[i][3] + bb0.w, 0.f);
            v1.x = fmaxf(acc[i][4] + bb1.x, 0.f);
            v1.y = fmaxf(acc[i][5] + bb1.y, 0.f);
            v1.z = fmaxf(acc[i][6] + bb1.z, 0.f);
            v1.w = fmaxf(acc[i][7] + bb1.w, 0.f);
            *(float4*)&O[gr * ldo + cb] = v0;
            *(float4*)&O[gr * ldo + cb + 4] = v1;
        }
    }
}

// ---------------- pooling ----------------
__global__ void k_zero_pool() {
    int i = blockIdx.x * blockDim.x + threadIdx.x;
    if (i < GG * 128) g_gsum[i] = 0.f;
    if (i < GG) g_gcnt[i] = 0.f;
}

__global__ __launch_bounds__(128) void k_pool(const int* __restrict__ batch, int n) {
    const int NPB = 512;
    int n0 = blockIdx.x * NPB;
    if (n0 >= n) return;
    int n1 = min(n0 + NPB, n);
    int d = threadIdx.x;  // 128 channels
    int cur = batch[n0];
    float acc = 0.f, cacc = 0.f;
    for (int nn = n0; nn < n1; nn++) {
        int g = batch[nn];
        if (g != cur) {
            atomicAdd(&g_gsum[cur * 128 + d], acc);
            if (d == 0) atomicAdd(&g_gcnt[cur], cacc);
            acc = 0.f; cacc = 0.f; cur = g;
        }
        acc += g_h2[nn * 128 + d];
        cacc += 1.f;
    }
    atomicAdd(&g_gsum[cur * 128 + d], acc);
    if (d == 0) atomicAdd(&g_gcnt[cur], cacc);
}

// ---------------- decoder: out[g] = (relu(gfeat@W1+b1))@W2 + b2 ----------
__global__ __launch_bounds__(64) void k_final(
    const float* __restrict__ W1, const float* __restrict__ b1,
    const float* __restrict__ W2, const float* __restrict__ b2,
    float* __restrict__ out) {
    int g = blockIdx.x;
    int c = threadIdx.x;  // 64
    __shared__ float sh[64];
    float inv = 1.f / fmaxf(g_gcnt[g], 1.f);
    float acc = 0.f;
#pragma unroll 4
    for (int k = 0; k < 128; k++) {
        float gf = g_gsum[g * 128 + k] * inv;
        acc += gf * W1[k * 64 + c];
    }
    acc = fmaxf(acc + b1[c], 0.f);
    sh[c] = acc * W2[c];
    __syncthreads();
    if (c < 32) {
        float v = sh[c] + sh[c + 32];
        for (int off = 16; off > 0; off >>= 1)
            v += __shfl_down_sync(0xffffffffu, v, off);
        if (c == 0) out[g] = v + b2[0];
    }
}

// ---------------- launch ----------------
extern "C" void kernel_launch(void* const* d_in, const int* in_sizes, int n_in,
                              void* d_out, int out_size) {
    const float* x       = (const float*)d_in[0];
    const int*   ei      = (const int*)d_in[1];
    const int*   batch   = (const int*)d_in[2];
    const float* conv_W  = (const float*)d_in[3];   // [4,64,64]
    const float* conv_b  = (const float*)d_in[4];   // [4,64]
    const float* bn_g    = (const float*)d_in[5];
    const float* bn_b    = (const float*)d_in[6];
    const float* bn_m    = (const float*)d_in[7];
    const float* bn_v    = (const float*)d_in[8];
    const float* enc_W1  = (const float*)d_in[9];   // [256,256]
    const float* enc_b1  = (const float*)d_in[10];  // [256]
    const float* enc_W2  = (const float*)d_in[11];  // [256,128]
    const float* enc_b2  = (const float*)d_in[12];  // [128]
    const float* dec_W1  = (const float*)d_in[13];  // [128,64]
    const float* dec_b1  = (const float*)d_in[14];  // [64]
    const float* dec_W2  = (const float*)d_in[15];  // [64,1]
    const float* dec_b2  = (const float*)d_in[16];  // [1]
    float* out = (float*)d_out;

    int n  = in_sizes[0] / 64;
    int ne = in_sizes[1] / 2;

    int nb1024 = (n + 1023) / 1024;
    int nb256  = (n + 255) / 256;
    int eb256  = (ne + 255) / 256;

    // GCN normalization + CSR build (once, reused by all 4 layers)
    k_init_cnt<<<nb256, 256>>>(n);
    k_deg<<<eb256, 256>>>(ei, ne);
    k_dis<<<nb256, 256>>>(n);
    k_scanA<<<nb1024, 1024>>>(n);
    k_scanB<<<1, 32>>>(nb1024);
    k_scanC<<<nb256, 256>>>(n, ne);
    k_scatter<<<eb256, 256>>>(ei, ne);

    // 4 GCN layers
    int convBlocks = (n + 63) / 64;
    int aggBlocks  = (n + 7) / 8;  // 8 warps per block
    for (int l = 0; l < 4; l++) {
        k_conv_gemm<<<convBlocks, 256>>>(x, conv_W + l * 64 * 64, n, l);
        k_agg<<<aggBlocks, 256>>>(n, l, conv_b + l * 64, bn_g + l * 64,
                                  bn_b + l * 64, bn_m + l * 64, bn_v + l * 64);
    }

    // encoder MLP
    dim3 g1((n + 127) / 128, 2);
    k_enc_gemm<<<g1, 256>>>(enc_W1, enc_b1, 256, 256, 0, n);
    dim3 g2((n + 127) / 128, 1);
    k_enc_gemm<<<g2, 256>>>(enc_W2, enc_b2, 256, 128, 1, n);

    // pooling + decoder
    k_zero_pool<<<(GG * 128 + 255) / 256, 256>>>();
    k_pool<<<(n + 511) / 512, 128>>>(batch, n);
    k_final<<<GG, 64>>>(dec_W1, dec_b1, dec_W2, dec_b2, out);
}

// round 2
// speedup vs baseline: 1.0517x; 1.0517x over previous
#include <cuda_runtime.h>
#include <cstdint>

// ---------------- problem constants ----------------
#define NN 100000
#define NE 3200000
#define GG 64

// ---------------- f32x2 packed FMA helpers (sm_100+ only, via PTX) --------
#define FMA_F32X2(d, a, b) \
    asm("fma.rn.f32x2 %0, %1, %2, %0;" : "+l"(d) : "l"(a), "l"(b))

__device__ __forceinline__ uint64_t dup_f32(float x) {
    uint64_t d;
    uint32_t u = __float_as_uint(x);
    asm("mov.b64 %0, {%1, %1};" : "=l"(d) : "r"(u));
    return d;
}

__device__ __forceinline__ void unpack_f32x2(uint64_t v, float& lo, float& hi) {
    uint32_t a, b;
    asm("mov.b64 {%0, %1}, %2;" : "=r"(a), "=r"(b) : "l"(v));
    lo = __uint_as_float(a);
    hi = __uint_as_float(b);
}

// ---------------- device scratch (no allocs allowed) ----------------
__device__ float g_y[NN * 64];          // dis-scaled x@W
__device__ float g_local[NN * 256];     // concat of 4 layer outputs
__device__ float g_h1[NN * 256];        // enc layer-1 output
__device__ float g_h2[NN * 128];        // enc layer-2 output
__device__ float g_dis[NN];
__device__ int   g_cnt[NN];
__device__ int   g_excl[NN];
__device__ int   g_rowptr[NN + 1];
__device__ int   g_woff[NN];
__device__ int   g_src[NE];
__device__ int   g_bsums[128];
__device__ float g_gsum[GG * 128];
__device__ float g_gcnt[GG];

// ---------------- degree / dis ----------------
__global__ void k_init_cnt(int n) {
    int i = blockIdx.x * blockDim.x + threadIdx.x;
    if (i < n) g_cnt[i] = 1;  // self loop
}

__global__ void k_deg(const int* __restrict__ ei, int ne) {
    int i = blockIdx.x * blockDim.x + threadIdx.x;
    if (i < ne) atomicAdd(&g_cnt[ei[ne + i]], 1);  // col = target
}

__global__ void k_dis(int n) {
    int i = blockIdx.x * blockDim.x + threadIdx.x;
    if (i < n) g_dis[i] = rsqrtf((float)g_cnt[i]);
}

// ---------------- prefix scan for CSR (counts = cnt-1 = in-degree) --------
__global__ void k_scanA(int n) {
    __shared__ int sh[1024];
    int tid = threadIdx.x;
    int i = blockIdx.x * 1024 + tid;
    int v = (i < n) ? (g_cnt[i] - 1) : 0;
    sh[tid] = v;
    __syncthreads();
    for (int off = 1; off < 1024; off <<= 1) {
        int t = (tid >= off) ? sh[tid - off] : 0;
        __syncthreads();
        sh[tid] += t;
        __syncthreads();
    }
    if (i < n) g_excl[i] = sh[tid] - v;  // exclusive within block
    if (tid == 1023) g_bsums[blockIdx.x] = sh[1023];
}

__global__ void k_scanB(int nb) {
    if (threadIdx.x == 0 && blockIdx.x == 0) {
        int run = 0;
        for (int b = 0; b < nb; b++) {
            int t = g_bsums[b];
            g_bsums[b] = run;
            run += t;
        }
    }
}

__global__ void k_scanC(int n, int ne) {
    int i = blockIdx.x * blockDim.x + threadIdx.x;
    if (i < n) {
        int rp = g_excl[i] + g_bsums[i >> 10];
        g_rowptr[i] = rp;
        g_woff[i] = rp;
    }
    if (i == 0) g_rowptr[n] = ne;
}

__global__ void k_scatter(const int* __restrict__ ei, int ne) {
    int i = blockIdx.x * blockDim.x + threadIdx.x;
    if (i < ne) {
        int c = ei[ne + i];
        int pos = atomicAdd(&g_woff[c], 1);
        g_src[pos] = ei[i];  // row = source
    }
}

// ---------------- conv GEMM: y = (Xin @ W_l) * dis[row] ----------------
// block: 64 rows x 64 cols, 256 threads, 4x4 per thread (f32x2 packed)
__global__ __launch_bounds__(256) void k_conv_gemm(
    const float* __restrict__ X0, const float* __restrict__ W,
    int n, int layer) {
    __shared__ float As[64][65];
    __shared__ float Ws[64][64];
    int tid = threadIdx.x;
    int rowBase = blockIdx.x * 64;

    for (int idx = tid; idx < 4096; idx += 256)
        Ws[idx >> 6][idx & 63] = W[idx];
    for (int idx = tid; idx < 4096; idx += 256) {
        int r = idx >> 6, k = idx & 63;
        int gr = rowBase + r;
        float v = 0.f;
        if (gr < n) {
            if (layer == 0) v = X0[gr * 64 + k];
            else            v = g_local[gr * 256 + (layer - 1) * 64 + k];
        }
        As[r][k] = v;
    }
    __syncthreads();

    int tx = tid & 15, ty = tid >> 4;
    int c4 = tx * 4, r0 = ty * 4;
    uint64_t acc2[4][2] = {};
#pragma unroll
    for (int k = 0; k < 64; k++) {
        ulonglong2 bq = *(const ulonglong2*)&Ws[k][c4];  // pairs (c,c+1),(c+2,c+3)
#pragma unroll
        for (int i = 0; i < 4; i++) {
            uint64_t ad = dup_f32(As[r0 + i][k]);
            FMA_F32X2(acc2[i][0], ad, bq.x);
            FMA_F32X2(acc2[i][1], ad, bq.y);
        }
    }
#pragma unroll
    for (int i = 0; i < 4; i++) {
        int gr = rowBase + r0 + i;
        if (gr < n) {
            float d = g_dis[gr];
            float4 v;
            unpack_f32x2(acc2[i][0], v.x, v.y);
            unpack_f32x2(acc2[i][1], v.z, v.w);
            v.x *= d; v.y *= d; v.z *= d; v.w *= d;
            *(float4*)&g_y[gr * 64 + c4] = v;
        }
    }
}

// ---------------- aggregation + BN + relu + skip (warp per node) ----------
__global__ __launch_bounds__(256) void k_agg(
    int n, int layer,
    const float* __restrict__ bias, const float* __restrict__ gamma,
    const float* __restrict__ beta, const float* __restrict__ mean,
    const float* __restrict__ var) {
    int warp = (blockIdx.x * blockDim.x + threadIdx.x) >> 5;
    int lane = threadIdx.x & 31;
    if (warp >= n) return;
    int c = warp;
    int start = g_rowptr[c], end = g_rowptr[c + 1];
    float acc0 = g_y[c * 64 + lane];          // self loop
    float acc1 = g_y[c * 64 + 32 + lane];
    for (int e = start; e < end; e++) {
        int r = g_src[e];
        acc0 += g_y[r * 64 + lane];
        acc1 += g_y[r * 64 + 32 + lane];
    }
    float dc = g_dis[c];
    int d0 = lane, d1 = lane + 32;

    float s0 = gamma[d0] * rsqrtf(var[d0] + 1e-5f);
    float s1 = gamma[d1] * rsqrtf(var[d1] + 1e-5f);
    float v0 = (acc0 * dc + bias[d0] - mean[d0]) * s0 + beta[d0];
    float v1 = (acc1 * dc + bias[d1] - mean[d1]) * s1 + beta[d1];
    v0 = fmaxf(v0, 0.f);
    v1 = fmaxf(v1, 0.f);
    if (layer == 2) {  // skip: += previous_outputs[0] (cols 0..63)
        v0 += g_local[c * 256 + d0];
        v1 += g_local[c * 256 + d1];
    }
    g_local[c * 256 + layer * 64 + d0] = v0;
    g_local[c * 256 + layer * 64 + d1] = v1;
}

// ---------------- encoder GEMMs: out = relu(A @ B + bias) ----------------
// BM=128, BN=128, BK=16; 256 threads; 8x8 per thread, f32x2 packed over N.
// mode 0: A=g_local (ld 256), out=g_h1 (ld 256)
// mode 1: A=g_h1    (ld 256), out=g_h2 (ld 128)
__global__ __launch_bounds__(256) void k_enc_gemm(
    const float* __restrict__ B, const float* __restrict__ bias,
    int K, int ncols, int mode, int n) {
    __shared__ float As[128][17];
    __shared__ float Bs[16][128];
    const float* A = (mode == 0) ? g_local : g_h1;
    float* O = (mode == 0) ? g_h1 : g_h2;
    const int lda = 256;
    const int ldo = (mode == 0) ? 256 : 128;
    int rowBase = blockIdx.x * 128;
    int colBase = blockIdx.y * 128;
    int tid = threadIdx.x;
    int tx = tid & 15, ty = tid >> 4;
    uint64_t acc2[8][4] = {};  // pairs over N: (c,c+1),(c+2,c+3),(c+4,c+5),(c+6,c+7)

    for (int kb = 0; kb < K; kb += 16) {
        for (int idx = tid; idx < 128 * 16; idx += 256) {
            int r = idx >> 4, k = idx & 15;
            int gr = rowBase + r;
            As[r][k] = (gr < n) ? A[gr * lda + kb + k] : 0.f;
        }
        for (int idx = tid; idx < 16 * 128; idx += 256) {
            int r = idx >> 7, cc = idx & 127;
            Bs[r][cc] = B[(kb + r) * ncols + colBase + cc];
        }
        __syncthreads();
#pragma unroll
        for (int k = 0; k < 16; k++) {
            ulonglong2 bq0 = *(const ulonglong2*)&Bs[k][tx * 8];
            ulonglong2 bq1 = *(const ulonglong2*)&Bs[k][tx * 8 + 4];
#pragma unroll
            for (int i = 0; i < 8; i++) {
                uint64_t ad = dup_f32(As[ty * 8 + i][k]);
                FMA_F32X2(acc2[i][0], ad, bq0.x);
                FMA_F32X2(acc2[i][1], ad, bq0.y);
                FMA_F32X2(acc2[i][2], ad, bq1.x);
                FMA_F32X2(acc2[i][3], ad, bq1.y);
            }
        }
        __syncthreads();
    }
    int cb = colBase + tx * 8;
    float4 bb0 = *(const float4*)&bias[cb];
    float4 bb1 = *(const float4*)&bias[cb + 4];
#pragma unroll
    for (int i = 0; i < 8; i++) {
        int gr = rowBase + ty * 8 + i;
        if (gr < n) {
            float4 v0, v1;
            unpack_f32x2(acc2[i][0], v0.x, v0.y);
            unpack_f32x2(acc2[i][1], v0.z, v0.w);
            unpack_f32x2(acc2[i][2], v1.x, v1.y);
            unpack_f32x2(acc2[i][3], v1.z, v1.w);
            v0.x = fmaxf(v0.x + bb0.x, 0.f);
            v0.y = fmaxf(v0.y + bb0.y, 0.f);
            v0.z = fmaxf(v0.z + bb0.z, 0.f);
            v0.w = fmaxf(v0.w + bb0.w, 0.f);
            v1.x = fmaxf(v1.x + bb1.x, 0.f);
            v1.y = fmaxf(v1.y + bb1.y, 0.f);
            v1.z = fmaxf(v1.z + bb1.z, 0.f);
            v1.w = fmaxf(v1.w + bb1.w, 0.f);
            *(float4*)&O[gr * ldo + cb] = v0;
            *(float4*)&O[gr * ldo + cb + 4] = v1;
        }
    }
}

// ---------------- pooling ----------------
__global__ void k_zero_pool() {
    int i = blockIdx.x * blockDim.x + threadIdx.x;
    if (i < GG * 128) g_gsum[i] = 0.f;
    if (i < GG) g_gcnt[i] = 0.f;
}

__global__ __launch_bounds__(128) void k_pool(const int* __restrict__ batch, int n) {
    const int NPB = 512;
    int n0 = blockIdx.x * NPB;
    if (n0 >= n) return;
    int n1 = min(n0 + NPB, n);
    int d = threadIdx.x;  // 128 channels
    int cur = batch[n0];
    float acc = 0.f, cacc = 0.f;
    for (int nn = n0; nn < n1; nn++) {
        int g = batch[nn];
        if (g != cur) {
            atomicAdd(&g_gsum[cur * 128 + d], acc);
            if (d == 0) atomicAdd(&g_gcnt[cur], cacc);
            acc = 0.f; cacc = 0.f; cur = g;
        }
        acc += g_h2[nn * 128 + d];
        cacc += 1.f;
    }
    atomicAdd(&g_gsum[cur * 128 + d], acc);
    if (d == 0) atomicAdd(&g_gcnt[cur], cacc);
}

// ---------------- decoder: out[g] = (relu(gfeat@W1+b1))@W2 + b2 ----------
__global__ __launch_bounds__(64) void k_final(
    const float* __restrict__ W1, const float* __restrict__ b1,
    const float* __restrict__ W2, const float* __restrict__ b2,
    float* __restrict__ out) {
    int g = blockIdx.x;
    int c = threadIdx.x;  // 64
    __shared__ float sh[64];
    float inv = 1.f / fmaxf(g_gcnt[g], 1.f);
    float acc = 0.f;
#pragma unroll 4
    for (int k = 0; k < 128; k++) {
        float gf = g_gsum[g * 128 + k] * inv;
        acc += gf * W1[k * 64 + c];
    }
    acc = fmaxf(acc + b1[c], 0.f);
    sh[c] = acc * W2[c];
    __syncthreads();
    if (c < 32) {
        float v = sh[c] + sh[c + 32];
        for (int off = 16; off > 0; off >>= 1)
            v += __shfl_down_sync(0xffffffffu, v, off);
        if (c == 0) out[g] = v + b2[0];
    }
}

// ---------------- launch ----------------
extern "C" void kernel_launch(void* const* d_in, const int* in_sizes, int n_in,
                              void* d_out, int out_size) {
    const float* x       = (const float*)d_in[0];
    const int*   ei      = (const int*)d_in[1];
    const int*   batch   = (const int*)d_in[2];
    const float* conv_W  = (const float*)d_in[3];   // [4,64,64]
    const float* conv_b  = (const float*)d_in[4];   // [4,64]
    const float* bn_g    = (const float*)d_in[5];
    const float* bn_b    = (const float*)d_in[6];
    const float* bn_m    = (const float*)d_in[7];
    const float* bn_v    = (const float*)d_in[8];
    const float* enc_W1  = (const float*)d_in[9];   // [256,256]
    const float* enc_b1  = (const float*)d_in[10];  // [256]
    const float* enc_W2  = (const float*)d_in[11];  // [256,128]
    const float* enc_b2  = (const float*)d_in[12];  // [128]
    const float* dec_W1  = (const float*)d_in[13];  // [128,64]
    const float* dec_b1  = (const float*)d_in[14];  // [64]
    const float* dec_W2  = (const float*)d_in[15];  // [64,1]
    const float* dec_b2  = (const float*)d_in[16];  // [1]
    float* out = (float*)d_out;

    int n  = in_sizes[0] / 64;
    int ne = in_sizes[1] / 2;

    int nb1024 = (n + 1023) / 1024;
    int nb256  = (n + 255) / 256;
    int eb256  = (ne + 255) / 256;

    // GCN normalization + CSR build (once, reused by all 4 layers)
    k_init_cnt<<<nb256, 256>>>(n);
    k_deg<<<eb256, 256>>>(ei, ne);
    k_dis<<<nb256, 256>>>(n);
    k_scanA<<<nb1024, 1024>>>(n);
    k_scanB<<<1, 32>>>(nb1024);
    k_scanC<<<nb256, 256>>>(n, ne);
    k_scatter<<<eb256, 256>>>(ei, ne);

    // 4 GCN layers
    int convBlocks = (n + 63) / 64;
    int aggBlocks  = (n + 7) / 8;  // 8 warps per block
    for (int l = 0; l < 4; l++) {
        k_conv_gemm<<<convBlocks, 256>>>(x, conv_W + l * 64 * 64, n, l);
        k_agg<<<aggBlocks, 256>>>(n, l, conv_b + l * 64, bn_g + l * 64,
                                  bn_b + l * 64, bn_m + l * 64, bn_v + l * 64);
    }

    // encoder MLP
    dim3 g1((n + 127) / 128, 2);
    k_enc_gemm<<<g1, 256>>>(enc_W1, enc_b1, 256, 256, 0, n);
    dim3 g2((n + 127) / 128, 1);
    k_enc_gemm<<<g2, 256>>>(enc_W2, enc_b2, 256, 128, 1, n);

    // pooling + decoder
    k_zero_pool<<<(GG * 128 + 255) / 256, 256>>>();
    k_pool<<<(n + 511) / 512, 128>>>(batch, n);
    k_final<<<GG, 64>>>(dec_W1, dec_b1, dec_W2, dec_b2, out);
}